// round 1
// baseline (speedup 1.0000x reference)
#include <cuda_runtime.h>
#include <cstdint>

// Problem constants (fixed by setup_inputs)
#define BB   4
#define CC   64
#define OO   64
#define HH   128
#define WW   128
#define HW   (HH * WW)          // 16384
#define KK   5
#define KK2  (KK * KK)          // 25
#define KROW (CC * KK2)         // 1600
#define PLANE_N (BB * OO)       // 256 (b,o) planes
#define OUT1 ((size_t)BB * OO * HW)   // 4194304 elements per output tensor

// -------- device scratch (no allocation allowed) --------
__device__ float g_s[BB * HW];        // channel-summed input
__device__ float g_denom[BB * HW];    // max(5x5 box sum, 5)
__device__ int   g_tap_cnt[OO];
__device__ float g_wsum[OO];
__device__ int   g_tap_k[OO * KROW];
__device__ float g_tap_w[OO * KROW];
__device__ float g_maxv[PLANE_N];

// -------- 1) sparsify W: one warp per output channel, deterministic ballot compaction
__global__ void k_sparsify(const float* __restrict__ Wl) {
    int o = blockIdx.x;
    int lane = threadIdx.x;
    const float* row = Wl + o * KROW;
    int base = 0;
    float psum = 0.f;
    for (int k0 = 0; k0 < KROW; k0 += 32) {
        int k = k0 + lane;                 // KROW % 32 == 0
        float w = row[k];
        psum += w;
        unsigned m = __ballot_sync(0xffffffffu, w != 0.f);
        if (w != 0.f) {
            int pos = base + __popc(m & ((1u << lane) - 1u));
            g_tap_k[o * KROW + pos] = k;
            g_tap_w[o * KROW + pos] = w;
        }
        base += __popc(m);
    }
    #pragma unroll
    for (int off = 16; off; off >>= 1)
        psum += __shfl_xor_sync(0xffffffffu, psum, off);
    if (lane == 0) { g_tap_cnt[o] = base; g_wsum[o] = psum; }
}

// -------- 2) channel sum: s[b,h,w] = sum_c x[b,c,h,w]
__global__ void k_chansum(const float* __restrict__ x) {
    int i = blockIdx.x * blockDim.x + threadIdx.x;   // 0..BB*HW-1
    if (i >= BB * HW) return;
    int b = i >> 14;
    int p = i & (HW - 1);
    const float* xb = x + (size_t)b * CC * HW + p;
    float s = 0.f;
    #pragma unroll
    for (int c = 0; c < CC; c++) s += xb[c * HW];
    g_s[i] = s;
}

// -------- 3) 5x5 box sum with zero pad, clamp to >= 5
__global__ void k_denom() {
    int i = blockIdx.x * blockDim.x + threadIdx.x;
    if (i >= BB * HW) return;
    int b = i >> 14;
    int p = i & (HW - 1);
    int h = p >> 7, w = p & (WW - 1);
    const float* sb = g_s + b * HW;
    float acc = 0.f;
    #pragma unroll
    for (int dj = -2; dj <= 2; dj++) {
        int hh = h + dj;
        if ((unsigned)hh >= (unsigned)HH) continue;
        #pragma unroll
        for (int dk = -2; dk <= 2; dk++) {
            int ww = w + dk;
            if ((unsigned)ww >= (unsigned)WW) continue;
            acc += sb[hh * WW + ww];
        }
    }
    g_denom[i] = fmaxf(acc, 5.0f);
}

// -------- 4) main: per-(b,o) plane, sparse conv + xn1 + plane max
__global__ __launch_bounds__(256) void k_main(const float* __restrict__ x,
                                              float* __restrict__ out0,
                                              float* __restrict__ out1) {
    int bo = blockIdx.x;                 // 0..255
    int b = bo >> 6, o = bo & 63;

    __shared__ int   s_cnt;
    __shared__ float s_w[KROW];
    __shared__ int   s_ck[KROW];         // packed: c<<8 | (dj+2)<<4 | (dk+2)
    __shared__ float s_red[8];

    if (threadIdx.x == 0) s_cnt = g_tap_cnt[o];
    __syncthreads();
    int cnt = s_cnt;
    for (int t = threadIdx.x; t < cnt; t += blockDim.x) {
        int k = g_tap_k[o * KROW + t];
        int c = k / KK2, r = k % KK2;
        int dj = r / KK, dk = r % KK;
        s_ck[t] = (c << 8) | (dj << 4) | dk;   // dj,dk stored as 0..4 (subtract 2 at use)
        s_w[t] = g_tap_w[o * KROW + t];
    }
    __syncthreads();

    float ws = g_wsum[o];
    float inv_ws = 1.f / (1e-10f + ws);
    const float* xb = x + (size_t)b * CC * HW;
    const float* dn = g_denom + b * HW;
    float mx = -3.4e38f;

    for (int i = threadIdx.x; i < HW; i += blockDim.x) {
        int h = i >> 7, w = i & (WW - 1);
        float xl = 0.f;
        for (int t = 0; t < cnt; t++) {
            int pk = s_ck[t];
            int c  = pk >> 8;
            int hh = h + ((pk >> 4) & 15) - 2;
            int ww = w + (pk & 15) - 2;
            if ((unsigned)hh < (unsigned)HH && (unsigned)ww < (unsigned)WW)
                xl += s_w[t] * xb[c * HW + hh * WW + ww];
        }
        size_t oidx = (size_t)bo * HW + i;
        out0[oidx] = xl;
        float xn1 = (xl / dn[i]) * inv_ws;
        out1[oidx] = xn1;
        mx = fmaxf(mx, xn1);
    }

    // block max reduction (256 threads)
    #pragma unroll
    for (int off = 16; off; off >>= 1)
        mx = fmaxf(mx, __shfl_xor_sync(0xffffffffu, mx, off));
    if ((threadIdx.x & 31) == 0) s_red[threadIdx.x >> 5] = mx;
    __syncthreads();
    if (threadIdx.x < 8) {
        float v = s_red[threadIdx.x];
        #pragma unroll
        for (int off = 4; off; off >>= 1)
            v = fmaxf(v, __shfl_xor_sync(0xffu, v, off));
        if (threadIdx.x == 0) g_maxv[bo] = v;
    }
}

// -------- 5) finalize: xn = xn1 / (1e-10 + plane_max), bin = (xn^3 >= 0.5)
__global__ void k_final(float* __restrict__ out1, float* __restrict__ out2) {
    size_t idx = (size_t)blockIdx.x * blockDim.x + threadIdx.x;
    if (idx >= OUT1) return;
    int bo = (int)(idx >> 14);
    float v = out1[idx] / (1e-10f + g_maxv[bo]);
    out1[idx] = v;
    out2[idx] = (v * v * v >= 0.5f) ? 1.0f : 0.0f;
}

extern "C" void kernel_launch(void* const* d_in, const int* in_sizes, int n_in,
                              void* d_out, int out_size) {
    const float* x  = (const float*)d_in[0];   // (4,64,128,128)
    const float* Wl = (const float*)d_in[1];   // (64,1600,1,1)
    float* out  = (float*)d_out;
    float* out0 = out;                 // x_lateral
    float* out1 = out + OUT1;          // xn
    float* out2 = out + 2 * OUT1;      // bin

    k_sparsify<<<OO, 32>>>(Wl);
    k_chansum<<<(BB * HW + 255) / 256, 256>>>(x);
    k_denom<<<(BB * HW + 255) / 256, 256>>>();
    k_main<<<PLANE_N, 256>>>(x, out0, out1);
    k_final<<<(unsigned)((OUT1 + 255) / 256), 256>>>(out1, out2);
}

// round 2
// speedup vs baseline: 3.1541x; 3.1541x over previous
#include <cuda_runtime.h>
#include <cstdint>
#include <cfloat>

#define BB   4
#define CC   64
#define OO   64
#define HH   128
#define WW   128
#define HW   (HH * WW)          // 16384
#define KK   5
#define KK2  (KK * KK)          // 25
#define KROW (CC * KK2)         // 1600
#define PLANE_N (BB * OO)       // 256
#define OUT1 ((size_t)BB * OO * HW)

// pixels per thread / blocks per plane in main & final
#define PPT      4
#define TPB      256
#define BLK_PER_PLANE (HW / (TPB * PPT))   // 16

// -------- device scratch --------
__device__ float g_s[BB * HW];        // channel-summed input
__device__ float g_rdn[BB * HW];      // 1 / max(5x5 box sum, 5)
__device__ int   g_tap_cnt[OO];
__device__ float g_wsum[OO];
__device__ int   g_tap_k[OO * KROW];
__device__ float g_tap_w[OO * KROW];
__device__ float g_maxv[PLANE_N];

__device__ __forceinline__ void atomicMaxF(float* a, float v) {
    if (v >= 0.f) atomicMax((int*)a, __float_as_int(v));
    else          atomicMin((unsigned int*)a, __float_as_uint(v));
}

// -------- 1) sparsify W --------
__global__ void k_sparsify(const float* __restrict__ Wl) {
    int o = blockIdx.x;
    int lane = threadIdx.x;
    const float* row = Wl + o * KROW;
    int base = 0;
    float psum = 0.f;
    for (int k0 = 0; k0 < KROW; k0 += 32) {
        int k = k0 + lane;
        float w = row[k];
        psum += w;
        unsigned m = __ballot_sync(0xffffffffu, w != 0.f);
        if (w != 0.f) {
            int pos = base + __popc(m & ((1u << lane) - 1u));
            g_tap_k[o * KROW + pos] = k;
            g_tap_w[o * KROW + pos] = w;
        }
        base += __popc(m);
    }
    #pragma unroll
    for (int off = 16; off; off >>= 1)
        psum += __shfl_xor_sync(0xffffffffu, psum, off);
    if (lane == 0) { g_tap_cnt[o] = base; g_wsum[o] = psum; }
}

// -------- 2) channel sum (float4, 4 px/thread) --------
__global__ void k_chansum(const float* __restrict__ x) {
    int t = blockIdx.x * blockDim.x + threadIdx.x;   // quad index
    int nq = BB * HW / 4;
    if (t >= nq) return;
    int b = t / (HW / 4);
    int q = t % (HW / 4);
    const float4* xb = (const float4*)(x + (size_t)b * CC * HW) + q;
    float4 s = make_float4(0.f, 0.f, 0.f, 0.f);
    #pragma unroll
    for (int c = 0; c < CC; c++) {
        float4 v = xb[c * (HW / 4)];
        s.x += v.x; s.y += v.y; s.z += v.z; s.w += v.w;
    }
    ((float4*)g_s)[t] = s;
}

// -------- 3) reciprocal denom + init plane maxes --------
__global__ void k_denom() {
    int i = blockIdx.x * blockDim.x + threadIdx.x;
    if (i < PLANE_N) g_maxv[i] = -FLT_MAX;
    if (i >= BB * HW) return;
    int b = i >> 14;
    int p = i & (HW - 1);
    int h = p >> 7, w = p & (WW - 1);
    const float* sb = g_s + b * HW;
    float acc = 0.f;
    #pragma unroll
    for (int dj = -2; dj <= 2; dj++) {
        int hh = h + dj;
        if ((unsigned)hh >= (unsigned)HH) continue;
        #pragma unroll
        for (int dk = -2; dk <= 2; dk++) {
            int ww = w + dk;
            if ((unsigned)ww >= (unsigned)WW) continue;
            acc += sb[hh * WW + ww];
        }
    }
    g_rdn[i] = 1.0f / fmaxf(acc, 5.0f);
}

// -------- 4) main: sparse conv + xn1 + plane max (16 blocks/plane, 4 px/thread) --------
__global__ __launch_bounds__(TPB) void k_main(const float* __restrict__ x,
                                              float* __restrict__ out0,
                                              float* __restrict__ out1) {
    int bo = blockIdx.y;                 // 0..255
    int b = bo >> 6, o = bo & 63;

    __shared__ float s_w[64];
    __shared__ int   s_ck[64];           // c<<8 | dj<<4 | dk  (dj,dk in 0..4)
    __shared__ int   s_cnt;
    __shared__ float s_red[TPB / 32];

    if (threadIdx.x == 0) s_cnt = g_tap_cnt[o];
    __syncthreads();
    int cnt = s_cnt;
    // generic tap staging (cap at 64 fast taps in smem; spill handled below)
    for (int t = threadIdx.x; t < min(cnt, 64); t += blockDim.x) {
        int k = g_tap_k[o * KROW + t];
        int c = k / KK2, r = k % KK2;
        s_ck[t] = (c << 8) | ((r / KK) << 4) | (r % KK);
        s_w[t] = g_tap_w[o * KROW + t];
    }
    __syncthreads();

    float inv_ws = 1.f / (1e-10f + g_wsum[o]);
    const float* xb = x + (size_t)b * CC * HW;
    const float* rdn = g_rdn + b * HW;

    int i0 = (blockIdx.x * TPB + threadIdx.x) * PPT;   // base pixel (quad)
    int h = i0 >> 7, w0 = i0 & (WW - 1);               // h uniform over quad

    float xl[PPT] = {0.f, 0.f, 0.f, 0.f};
    int ncached = min(cnt, 64);
    for (int t = 0; t < ncached; t++) {
        int pk = s_ck[t];
        float wt = s_w[t];
        int c  = pk >> 8;
        int hh = h + ((pk >> 4) & 15) - 2;
        int dk = (pk & 15) - 2;
        if ((unsigned)hh < (unsigned)HH) {
            const float* src = xb + c * HW + hh * WW;
            #pragma unroll
            for (int u = 0; u < PPT; u++) {
                int ww = w0 + u + dk;
                if ((unsigned)ww < (unsigned)WW) xl[u] += wt * src[ww];
            }
        }
    }
    // rare spill path (cnt > 64): read taps straight from gmem
    for (int t = 64; t < cnt; t++) {
        int k = g_tap_k[o * KROW + t];
        float wt = g_tap_w[o * KROW + t];
        int c = k / KK2, r = k % KK2;
        int hh = h + r / KK - 2;
        int dk = r % KK - 2;
        if ((unsigned)hh < (unsigned)HH) {
            const float* src = xb + c * HW + hh * WW;
            #pragma unroll
            for (int u = 0; u < PPT; u++) {
                int ww = w0 + u + dk;
                if ((unsigned)ww < (unsigned)WW) xl[u] += wt * src[ww];
            }
        }
    }

    size_t oidx = (size_t)bo * HW + i0;
    float4 o0 = make_float4(xl[0], xl[1], xl[2], xl[3]);
    *(float4*)(out0 + oidx) = o0;

    float xn[PPT];
    float mx = -FLT_MAX;
    #pragma unroll
    for (int u = 0; u < PPT; u++) {
        xn[u] = xl[u] * rdn[i0 + u] * inv_ws;
        mx = fmaxf(mx, xn[u]);
    }
    *(float4*)(out1 + oidx) = make_float4(xn[0], xn[1], xn[2], xn[3]);

    // block max -> one atomic per block
    #pragma unroll
    for (int off = 16; off; off >>= 1)
        mx = fmaxf(mx, __shfl_xor_sync(0xffffffffu, mx, off));
    if ((threadIdx.x & 31) == 0) s_red[threadIdx.x >> 5] = mx;
    __syncthreads();
    if (threadIdx.x == 0) {
        float v = s_red[0];
        #pragma unroll
        for (int j = 1; j < TPB / 32; j++) v = fmaxf(v, s_red[j]);
        atomicMaxF(&g_maxv[bo], v);
    }
}

// -------- 5) finalize (float4, 4 px/thread) --------
__global__ __launch_bounds__(TPB) void k_final(float* __restrict__ out1,
                                               float* __restrict__ out2) {
    int bo = blockIdx.y;
    float r = 1.0f / (1e-10f + g_maxv[bo]);
    size_t base = (size_t)bo * HW + (size_t)(blockIdx.x * TPB + threadIdx.x) * PPT;
    float4 v = *(float4*)(out1 + base);
    v.x *= r; v.y *= r; v.z *= r; v.w *= r;
    *(float4*)(out1 + base) = v;
    float4 bn;
    bn.x = (v.x * v.x * v.x >= 0.5f) ? 1.0f : 0.0f;
    bn.y = (v.y * v.y * v.y >= 0.5f) ? 1.0f : 0.0f;
    bn.z = (v.z * v.z * v.z >= 0.5f) ? 1.0f : 0.0f;
    bn.w = (v.w * v.w * v.w >= 0.5f) ? 1.0f : 0.0f;
    *(float4*)(out2 + base) = bn;
}

extern "C" void kernel_launch(void* const* d_in, const int* in_sizes, int n_in,
                              void* d_out, int out_size) {
    const float* x  = (const float*)d_in[0];
    const float* Wl = (const float*)d_in[1];
    float* out  = (float*)d_out;
    float* out0 = out;
    float* out1 = out + OUT1;
    float* out2 = out + 2 * OUT1;

    k_sparsify<<<OO, 32>>>(Wl);
    k_chansum<<<(BB * HW / 4 + 255) / 256, 256>>>(x);
    k_denom<<<(BB * HW + 255) / 256, 256>>>();
    dim3 gmain(BLK_PER_PLANE, PLANE_N);
    k_main<<<gmain, TPB>>>(x, out0, out1);
    k_final<<<gmain, TPB>>>(out1, out2);
}